// round 7
// baseline (speedup 1.0000x reference)
#include <cuda_runtime.h>

#define NB 4096
#define NT 512
#define OBS 2
#define LAT 4
#define NH 20
#define RNNH 25

// output layout: pred_x (B,T,OBS) | z0 (B,LAT) | qz0_mean | qz0_logvar
#define OFF_Z0   (NB * NT * OBS)
#define OFF_MEAN (OFF_Z0 + NB * LAT)
#define OFF_LV   (OFF_MEAN + NB * LAT)

// scratch: latent trajectory (B, T, LAT)
__device__ float g_predz[NB * NT * LAT];

typedef unsigned long long u64;

// ---- packed f32x2 helpers (SASS FFMA2 path) -------------------------------
__device__ __forceinline__ u64 pack2(float lo, float hi) {
    u64 r; asm("mov.b64 %0, {%1,%2};" : "=l"(r) : "f"(lo), "f"(hi)); return r;
}
__device__ __forceinline__ u64 dup2(float x) { return pack2(x, x); }
__device__ __forceinline__ void unpack2(u64 p, float& lo, float& hi) {
    asm("mov.b64 {%0,%1}, %2;" : "=f"(lo), "=f"(hi) : "l"(p));
}
__device__ __forceinline__ u64 fma2(u64 a, u64 b, u64 c) {
    u64 d; asm("fma.rn.f32x2 %0, %1, %2, %3;" : "=l"(d) : "l"(a), "l"(b), "l"(c));
    return d;
}
__device__ __forceinline__ u64 add2(u64 a, u64 b) {
    u64 d; asm("add.rn.f32x2 %0, %1, %2;" : "=l"(d) : "l"(a), "l"(b)); return d;
}

__device__ __forceinline__ float elu_f(float x) {
    return fmaxf(x, 0.f) + (__expf(fminf(x, 0.f)) - 1.f);
}
__device__ __forceinline__ u64 elu2(u64 p) {
    float a, b; unpack2(p, a, b);
    return pack2(elu_f(a), elu_f(b));
}
__device__ __forceinline__ float fast_tanh(float x) {
    float a = fabsf(x);
    float e = __expf(-2.f * a);
    float r = __fdividef(1.f - e, 1.f + e);
    return copysignf(r, x);
}

// ---------------------------------------------------------------------------
// Kernel 1: backward RNN scan + encoder head + z0.
// ONE WARP PER BLOCK (even SM distribution). One warp = TWO batches (f32x2).
// Lane j (<25) owns hidden unit j. x prefetched one step ahead.
// ---------------------------------------------------------------------------
__global__ __launch_bounds__(32)
void rnn_kernel(const float* __restrict__ trajs,
                const float* __restrict__ eps,
                const float* __restrict__ i2h_w,
                const float* __restrict__ i2h_b,
                const float* __restrict__ h2o_w,
                const float* __restrict__ h2o_b,
                float* __restrict__ out)
{
    const int lane = threadIdx.x;
    const int gw   = blockIdx.x;                // 0..2047
    const int b0   = 2 * gw;
    const int b1   = b0 + 1;

    __shared__ __align__(16) float2 hs[2][28];  // double-buffered packed h

    const int j = (lane < RNNH) ? lane : 0;
    u64 wx0 = dup2(i2h_w[j]);
    u64 wx1 = dup2(i2h_w[RNNH + j]);
    u64 wh[28];
#pragma unroll
    for (int i = 0; i < RNNH; ++i) wh[i] = dup2(i2h_w[(2 + i) * RNNH + j]);
#pragma unroll
    for (int i = RNNH; i < 28; ++i) wh[i] = 0ull;
    u64 bb = dup2(i2h_b[j]);

    if (lane < 28) {
        hs[0][lane] = make_float2(0.f, 0.f);
        hs[1][lane] = make_float2(0.f, 0.f);
    }
    __syncwarp();

    const float2* xrow0 = (const float2*)trajs + (size_t)b0 * NT;
    const float2* xrow1 = (const float2*)trajs + (size_t)b1 * NT;

    float2 nx0 = xrow0[NT - 1];
    float2 nx1 = xrow1[NT - 1];

    int cur = 0;
    for (int t = NT - 1; t >= 0; --t) {
        float2 x0 = nx0, x1 = nx1;
        if (t > 0) { nx0 = xrow0[t - 1]; nx1 = xrow1[t - 1]; }  // prefetch

        u64 acc = fma2(pack2(x0.x, x1.x), wx0,
                  fma2(pack2(x0.y, x1.y), wx1, bb));
        const ulonglong2* hb = (const ulonglong2*)hs[cur];
#pragma unroll
        for (int q = 0; q < 14; ++q) {          // 14 * 2 packed units = 28
            ulonglong2 hv = hb[q];
            acc = fma2(hv.x, wh[2 * q + 0], acc);
            acc = fma2(hv.y, wh[2 * q + 1], acc);
        }
        float alo, ahi; unpack2(acc, alo, ahi);
        if (lane < RNNH)
            hs[cur ^ 1][lane] = make_float2(fast_tanh(alo), fast_tanh(ahi));
        __syncwarp();
        cur ^= 1;
    }

    // encoder head: out8 = h_last @ h2o_w + b  (lanes 0..7, packed 2 batches)
    u64 o = 0ull;
    if (lane < 8) {
        o = dup2(h2o_b[lane]);
        const float2* hl = hs[cur];
#pragma unroll
        for (int i = 0; i < RNNH; ++i) {
            float2 h = hl[i];
            o = fma2(pack2(h.x, h.y), dup2(h2o_w[i * 8 + lane]), o);
        }
    }
    u64 lv = __shfl_sync(0xffffffffu, o, lane + 4);
    if (lane < LAT) {
        float m0, m1, l0, l1;
        unpack2(o, m0, m1);
        unpack2(lv, l0, l1);
        float z00 = fmaf(eps[b0 * LAT + lane], expf(0.5f * l0), m0);
        float z01 = fmaf(eps[b1 * LAT + lane], expf(0.5f * l1), m1);
        out[OFF_MEAN + b0 * LAT + lane] = m0;
        out[OFF_MEAN + b1 * LAT + lane] = m1;
        out[OFF_Z0 + b0 * LAT + lane] = z00;
        out[OFF_Z0 + b1 * LAT + lane] = z01;
        g_predz[(size_t)b0 * NT * LAT + lane] = z00;
        g_predz[(size_t)b1 * NT * LAT + lane] = z01;
    }
    if (lane >= 4 && lane < 8) {
        float l0, l1; unpack2(o, l0, l1);
        out[OFF_LV + b0 * LAT + (lane - 4)] = l0;
        out[OFF_LV + b1 * LAT + (lane - 4)] = l1;
    }
}

// ---------------------------------------------------------------------------
// Kernel 2: RK4 ODE scan — round-3 structure, ONE WARP PER BLOCK.
// One warp = TWO batches (packed f32x2). Lane j (<20) owns hidden unit j.
// Shared per-warp exchange: sw[0..3]=z_t, sw[4..23]=u1, sw[24..43]=u2.
// Layer3 split over 8 lanes + shfl reduce.
// ---------------------------------------------------------------------------
__global__ __launch_bounds__(32)
void ode_kernel(const float* __restrict__ ts,
                const float* __restrict__ f1_w, const float* __restrict__ f1_b,
                const float* __restrict__ f2_w, const float* __restrict__ f2_b,
                const float* __restrict__ f3_w, const float* __restrict__ f3_b)
{
    const int lane = threadIdx.x;
    const int gw   = blockIdx.x;                // 0..2047
    const int b0   = 2 * gw;
    const int b1   = b0 + 1;

    __shared__ __align__(16) float2 sw[48];
    __shared__ float s_dt[NT];

    for (int i = lane; i < NT - 1; i += 32)
        s_dt[i] = ts[i + 1] - ts[i];
    __syncwarp();

    const int j = (lane < NH) ? lane : 0;
    u64 w1r[LAT];
#pragma unroll
    for (int i = 0; i < LAT; ++i) w1r[i] = dup2(f1_w[i * NH + j]);
    u64 b1r = dup2(f1_b[j]);
    u64 w2c[NH];
#pragma unroll
    for (int i = 0; i < NH; ++i) w2c[i] = dup2(f2_w[i * NH + j]);
    u64 b2r = dup2(f2_b[j]);

    // layer3: lanes 0..7; lane l computes output (l&3) over inputs [(l>>2)*10,+10)
    const int l4 = lane & 3;
    const int half = (lane >> 2) & 1;
    u64 w3c[10];
#pragma unroll
    for (int i = 0; i < 10; ++i) w3c[i] = dup2(f3_w[(half * 10 + i) * LAT + l4]);
    u64 b3r = (half == 0) ? dup2(f3_b[l4]) : 0ull;

    u64 zc = 0ull, kacc = 0ull;
    if (lane < LAT) {
        zc = pack2(g_predz[(size_t)b0 * NT * LAT + lane],
                   g_predz[(size_t)b1 * NT * LAT + lane]);
        float lo, hi; unpack2(zc, lo, hi);
        sw[lane] = make_float2(lo, hi);
    }
    __syncwarp();

    for (int t = 0; t < NT - 1; ++t) {
        const float dt = s_dt[t];
        const u64 hdt = dup2(0.5f * dt);
        const u64 fdt = dup2(dt);
        const u64 sdt = dup2(dt * (1.f / 6.f));
#pragma unroll
        for (int e = 0; e < 4; ++e) {
            // layer1
            const ulonglong2* ztv = (const ulonglong2*)sw;
            ulonglong2 za = ztv[0], zb = ztv[1];
            u64 a1 = fma2(za.x, w1r[0],
                     fma2(za.y, w1r[1],
                     fma2(zb.x, w1r[2],
                     fma2(zb.y, w1r[3], b1r))));
            a1 = elu2(a1);
            if (lane < NH) ((u64*)(sw + 4))[lane] = a1;
            __syncwarp();

            // layer2
            u64 acc = b2r;
            const ulonglong2* u1v = (const ulonglong2*)(sw + 4);
#pragma unroll
            for (int q = 0; q < 10; ++q) {
                ulonglong2 v = u1v[q];
                acc = fma2(v.x, w2c[2 * q + 0], acc);
                acc = fma2(v.y, w2c[2 * q + 1], acc);
            }
            acc = elu2(acc);
            if (lane < NH) ((u64*)(sw + 24))[lane] = acc;
            __syncwarp();

            // layer3 (lanes 0..7): partial over 10 inputs, shfl-reduce
            u64 kk = b3r;
            {
                const ulonglong2* u2v = (const ulonglong2*)(sw + 24 + half * 10);
#pragma unroll
                for (int q = 0; q < 5; ++q) {
                    ulonglong2 v = u2v[q];
                    kk = fma2(v.x, w3c[2 * q + 0], kk);
                    kk = fma2(v.y, w3c[2 * q + 1], kk);
                }
            }
            kk = add2(kk, __shfl_down_sync(0xffffffffu, kk, 4));

            if (lane < LAT) {
                u64 ztn;
                if (e == 0)      { kacc = kk;                        ztn = fma2(hdt, kk, zc); }
                else if (e == 1) { kacc = fma2(dup2(2.f), kk, kacc); ztn = fma2(hdt, kk, zc); }
                else if (e == 2) { kacc = fma2(dup2(2.f), kk, kacc); ztn = fma2(fdt, kk, zc); }
                else             { kacc = add2(kacc, kk);
                                   zc  = fma2(sdt, kacc, zc);
                                   ztn = zc; }
                ((u64*)sw)[lane] = ztn;
            }
            __syncwarp();
        }
        if (lane < LAT) {
            float lo, hi; unpack2(zc, lo, hi);
            g_predz[((size_t)b0 * NT + t + 1) * LAT + lane] = lo;
            g_predz[((size_t)b1 * NT + t + 1) * LAT + lane] = hi;
        }
    }
}

// ---------------------------------------------------------------------------
// Kernel 3: decoder — fully parallel over (b, t).
// ---------------------------------------------------------------------------
__global__ __launch_bounds__(256)
void dec_kernel(const float* __restrict__ d1_w, const float* __restrict__ d1_b,
                const float* __restrict__ d2_w, const float* __restrict__ d2_b,
                float* __restrict__ out)
{
    __shared__ float sw1[LAT * NH], sb1[NH], sw2[NH * OBS], sb2[OBS];
    if (threadIdx.x < LAT * NH) sw1[threadIdx.x] = d1_w[threadIdx.x];
    if (threadIdx.x < NH)       sb1[threadIdx.x] = d1_b[threadIdx.x];
    if (threadIdx.x < NH * OBS) sw2[threadIdx.x] = d2_w[threadIdx.x];
    if (threadIdx.x < OBS)      sb2[threadIdx.x] = d2_b[threadIdx.x];
    __syncthreads();

    int idx = blockIdx.x * blockDim.x + threadIdx.x;   // < NB*NT
    float4 z = *(const float4*)&g_predz[(size_t)idx * LAT];

    float acc0 = sb2[0], acc1 = sb2[1];
#pragma unroll
    for (int jj = 0; jj < NH; ++jj) {
        float h = fmaf(z.x, sw1[0 * NH + jj],
                  fmaf(z.y, sw1[1 * NH + jj],
                  fmaf(z.z, sw1[2 * NH + jj],
                  fmaf(z.w, sw1[3 * NH + jj], sb1[jj]))));
        h = fmaxf(h, 0.f);
        acc0 = fmaf(h, sw2[jj * OBS + 0], acc0);
        acc1 = fmaf(h, sw2[jj * OBS + 1], acc1);
    }
    ((float2*)out)[idx] = make_float2(acc0, acc1);
}

// ---------------------------------------------------------------------------
extern "C" void kernel_launch(void* const* d_in, const int* in_sizes, int n_in,
                              void* d_out, int out_size)
{
    const float* samp_trajs = (const float*)d_in[0];
    const float* samp_ts    = (const float*)d_in[1];
    const float* epsilon    = (const float*)d_in[2];
    const float* i2h_w      = (const float*)d_in[3];
    const float* i2h_b      = (const float*)d_in[4];
    const float* h2o_w      = (const float*)d_in[5];
    const float* h2o_b      = (const float*)d_in[6];
    const float* f1_w       = (const float*)d_in[7];
    const float* f1_b       = (const float*)d_in[8];
    const float* f2_w       = (const float*)d_in[9];
    const float* f2_b       = (const float*)d_in[10];
    const float* f3_w       = (const float*)d_in[11];
    const float* f3_b       = (const float*)d_in[12];
    const float* d1_w       = (const float*)d_in[13];
    const float* d1_b       = (const float*)d_in[14];
    const float* d2_w       = (const float*)d_in[15];
    const float* d2_b       = (const float*)d_in[16];
    float* out = (float*)d_out;

    rnn_kernel<<<NB / 2, 32>>>(samp_trajs, epsilon, i2h_w, i2h_b, h2o_w, h2o_b, out);
    ode_kernel<<<NB / 2, 32>>>(samp_ts, f1_w, f1_b, f2_w, f2_b, f3_w, f3_b);
    dec_kernel<<<(NB * NT) / 256, 256>>>(d1_w, d1_b, d2_w, d2_b, out);
}

// round 8
// speedup vs baseline: 1.6054x; 1.6054x over previous
#include <cuda_runtime.h>

#define NB 4096
#define NT 512
#define OBS 2
#define LAT 4
#define NH 20
#define RNNH 25

#define NWPB 7           // warps per block (7*296 = 2072 slots >= 2048)
#define NBLK 296         // 2 blocks per SM exactly

// output layout: pred_x (B,T,OBS) | z0 (B,LAT) | qz0_mean | qz0_logvar
#define OFF_Z0   (NB * NT * OBS)
#define OFF_MEAN (OFF_Z0 + NB * LAT)
#define OFF_LV   (OFF_MEAN + NB * LAT)

// scratch: latent trajectory (B, T, LAT)
__device__ float g_predz[NB * NT * LAT];

typedef unsigned long long u64;

// ---- packed f32x2 helpers (SASS FFMA2 path) -------------------------------
__device__ __forceinline__ u64 pack2(float lo, float hi) {
    u64 r; asm("mov.b64 %0, {%1,%2};" : "=l"(r) : "f"(lo), "f"(hi)); return r;
}
__device__ __forceinline__ u64 dup2(float x) { return pack2(x, x); }
__device__ __forceinline__ void unpack2(u64 p, float& lo, float& hi) {
    asm("mov.b64 {%0,%1}, %2;" : "=f"(lo), "=f"(hi) : "l"(p));
}
__device__ __forceinline__ u64 fma2(u64 a, u64 b, u64 c) {
    u64 d; asm("fma.rn.f32x2 %0, %1, %2, %3;" : "=l"(d) : "l"(a), "l"(b), "l"(c));
    return d;
}
__device__ __forceinline__ u64 add2(u64 a, u64 b) {
    u64 d; asm("add.rn.f32x2 %0, %1, %2;" : "=l"(d) : "l"(a), "l"(b)); return d;
}

__device__ __forceinline__ float elu_f(float x) {
    return fmaxf(x, 0.f) + (__expf(fminf(x, 0.f)) - 1.f);
}
__device__ __forceinline__ u64 elu2(u64 p) {
    float a, b; unpack2(p, a, b);
    return pack2(elu_f(a), elu_f(b));
}
__device__ __forceinline__ float fast_tanh(float x) {
    float a = fabsf(x);
    float e = __expf(-2.f * a);
    float r = __fdividef(1.f - e, 1.f + e);
    return copysignf(r, x);
}

// ---------------------------------------------------------------------------
// Kernel 1: backward RNN scan + encoder head + z0.
// 7 warps/block, grid 296 (2 CTAs per SM exactly). One warp = TWO batches.
// Lane j (<25) owns hidden unit j. x prefetched one step ahead.
// Recurrence uses 2 partial accumulator chains.
// ---------------------------------------------------------------------------
__global__ __launch_bounds__(NWPB * 32)
void rnn_kernel(const float* __restrict__ trajs,
                const float* __restrict__ eps,
                const float* __restrict__ i2h_w,
                const float* __restrict__ i2h_b,
                const float* __restrict__ h2o_w,
                const float* __restrict__ h2o_b,
                float* __restrict__ out)
{
    const int wIn  = threadIdx.x >> 5;
    const int lane = threadIdx.x & 31;
    const int gw   = blockIdx.x * NWPB + wIn;   // 0..2071
    if (gw >= NB / 2) return;                   // no block-level sync in this kernel
    const int b0   = 2 * gw;
    const int b1   = b0 + 1;

    __shared__ __align__(16) float2 hs[NWPB][2][28];   // double-buffered packed h

    const int j = (lane < RNNH) ? lane : 0;
    u64 wx0 = dup2(i2h_w[j]);
    u64 wx1 = dup2(i2h_w[RNNH + j]);
    u64 wh[28];
#pragma unroll
    for (int i = 0; i < RNNH; ++i) wh[i] = dup2(i2h_w[(2 + i) * RNNH + j]);
#pragma unroll
    for (int i = RNNH; i < 28; ++i) wh[i] = 0ull;
    u64 bb = dup2(i2h_b[j]);

    if (lane < 28) {
        hs[wIn][0][lane] = make_float2(0.f, 0.f);
        hs[wIn][1][lane] = make_float2(0.f, 0.f);
    }
    __syncwarp();

    const float2* xrow0 = (const float2*)trajs + (size_t)b0 * NT;
    const float2* xrow1 = (const float2*)trajs + (size_t)b1 * NT;

    float2 nx0 = xrow0[NT - 1];
    float2 nx1 = xrow1[NT - 1];

    int cur = 0;
    for (int t = NT - 1; t >= 0; --t) {
        float2 x0 = nx0, x1 = nx1;
        if (t > 0) { nx0 = xrow0[t - 1]; nx1 = xrow1[t - 1]; }  // prefetch

        // two partial chains of 14 FFMA2 each
        u64 a0 = fma2(pack2(x0.x, x1.x), wx0,
                 fma2(pack2(x0.y, x1.y), wx1, bb));
        u64 a1 = 0ull;
        const ulonglong2* hb = (const ulonglong2*)hs[wIn][cur];
#pragma unroll
        for (int q = 0; q < 14; ++q) {
            ulonglong2 hv = hb[q];
            a0 = fma2(hv.x, wh[2 * q + 0], a0);
            a1 = fma2(hv.y, wh[2 * q + 1], a1);
        }
        u64 acc = add2(a0, a1);
        float alo, ahi; unpack2(acc, alo, ahi);
        if (lane < RNNH)
            hs[wIn][cur ^ 1][lane] = make_float2(fast_tanh(alo), fast_tanh(ahi));
        __syncwarp();
        cur ^= 1;
    }

    // encoder head: out8 = h_last @ h2o_w + b  (lanes 0..7, packed 2 batches)
    u64 o = 0ull;
    if (lane < 8) {
        o = dup2(h2o_b[lane]);
        const float2* hl = hs[wIn][cur];
#pragma unroll
        for (int i = 0; i < RNNH; ++i) {
            float2 h = hl[i];
            o = fma2(pack2(h.x, h.y), dup2(h2o_w[i * 8 + lane]), o);
        }
    }
    u64 lv = __shfl_sync(0xffffffffu, o, lane + 4);
    if (lane < LAT) {
        float m0, m1, l0, l1;
        unpack2(o, m0, m1);
        unpack2(lv, l0, l1);
        float z00 = fmaf(eps[b0 * LAT + lane], expf(0.5f * l0), m0);
        float z01 = fmaf(eps[b1 * LAT + lane], expf(0.5f * l1), m1);
        out[OFF_MEAN + b0 * LAT + lane] = m0;
        out[OFF_MEAN + b1 * LAT + lane] = m1;
        out[OFF_Z0 + b0 * LAT + lane] = z00;
        out[OFF_Z0 + b1 * LAT + lane] = z01;
        g_predz[(size_t)b0 * NT * LAT + lane] = z00;
        g_predz[(size_t)b1 * NT * LAT + lane] = z01;
    }
    if (lane >= 4 && lane < 8) {
        float l0, l1; unpack2(o, l0, l1);
        out[OFF_LV + b0 * LAT + (lane - 4)] = l0;
        out[OFF_LV + b1 * LAT + (lane - 4)] = l1;
    }
}

// ---------------------------------------------------------------------------
// Kernel 2: RK4 ODE scan — round-3 structure, 7 warps/block, grid 296.
// One warp = TWO batches (packed f32x2). Lane j (<20) owns hidden unit j.
// Shared per-warp exchange: sw[0..3]=z_t, sw[4..23]=u1, sw[24..43]=u2.
// Layer2: 2 accumulator chains. Layer3: 8 lanes, 2 chains + shfl reduce.
// ---------------------------------------------------------------------------
__global__ __launch_bounds__(NWPB * 32)
void ode_kernel(const float* __restrict__ ts,
                const float* __restrict__ f1_w, const float* __restrict__ f1_b,
                const float* __restrict__ f2_w, const float* __restrict__ f2_b,
                const float* __restrict__ f3_w, const float* __restrict__ f3_b)
{
    const int wIn  = threadIdx.x >> 5;
    const int lane = threadIdx.x & 31;
    const int gw   = blockIdx.x * NWPB + wIn;   // 0..2071

    __shared__ __align__(16) float2 sbuf[NWPB][48];
    __shared__ float s_dt[NT];

    for (int i = threadIdx.x; i < NT - 1; i += blockDim.x)
        s_dt[i] = ts[i + 1] - ts[i];
    __syncthreads();
    if (gw >= NB / 2) return;                   // after block sync

    const int b0 = 2 * gw;
    const int b1 = b0 + 1;
    float2* sw = sbuf[wIn];

    const int j = (lane < NH) ? lane : 0;
    u64 w1r[LAT];
#pragma unroll
    for (int i = 0; i < LAT; ++i) w1r[i] = dup2(f1_w[i * NH + j]);
    u64 b1r = dup2(f1_b[j]);
    u64 w2c[NH];
#pragma unroll
    for (int i = 0; i < NH; ++i) w2c[i] = dup2(f2_w[i * NH + j]);
    u64 b2r = dup2(f2_b[j]);

    // layer3: lanes 0..7; lane l computes output (l&3) over inputs [(l>>2)*10,+10)
    const int l4 = lane & 3;
    const int half = (lane >> 2) & 1;
    u64 w3c[10];
#pragma unroll
    for (int i = 0; i < 10; ++i) w3c[i] = dup2(f3_w[(half * 10 + i) * LAT + l4]);
    u64 b3r = (half == 0) ? dup2(f3_b[l4]) : 0ull;

    u64 zc = 0ull, kacc = 0ull;
    if (lane < LAT) {
        zc = pack2(g_predz[(size_t)b0 * NT * LAT + lane],
                   g_predz[(size_t)b1 * NT * LAT + lane]);
        float lo, hi; unpack2(zc, lo, hi);
        sw[lane] = make_float2(lo, hi);
    }
    __syncwarp();

    for (int t = 0; t < NT - 1; ++t) {
        const float dt = s_dt[t];
        const u64 hdt = dup2(0.5f * dt);
        const u64 fdt = dup2(dt);
        const u64 sdt = dup2(dt * (1.f / 6.f));
#pragma unroll
        for (int e = 0; e < 4; ++e) {
            // layer1
            const ulonglong2* ztv = (const ulonglong2*)sw;
            ulonglong2 za = ztv[0], zb = ztv[1];
            u64 a1 = fma2(za.x, w1r[0],
                     fma2(za.y, w1r[1],
                     fma2(zb.x, w1r[2],
                     fma2(zb.y, w1r[3], b1r))));
            a1 = elu2(a1);
            if (lane < NH) ((u64*)(sw + 4))[lane] = a1;
            __syncwarp();

            // layer2 — two partial chains of 10
            u64 c0 = b2r, c1 = 0ull;
            const ulonglong2* u1v = (const ulonglong2*)(sw + 4);
#pragma unroll
            for (int q = 0; q < 10; ++q) {
                ulonglong2 v = u1v[q];
                c0 = fma2(v.x, w2c[2 * q + 0], c0);
                c1 = fma2(v.y, w2c[2 * q + 1], c1);
            }
            u64 acc = elu2(add2(c0, c1));
            if (lane < NH) ((u64*)(sw + 24))[lane] = acc;
            __syncwarp();

            // layer3 (lanes 0..7): two partial chains of 5, shfl-reduce
            u64 p0 = b3r, p1 = 0ull;
            {
                const ulonglong2* u2v = (const ulonglong2*)(sw + 24 + half * 10);
#pragma unroll
                for (int q = 0; q < 5; ++q) {
                    ulonglong2 v = u2v[q];
                    p0 = fma2(v.x, w3c[2 * q + 0], p0);
                    p1 = fma2(v.y, w3c[2 * q + 1], p1);
                }
            }
            u64 kk = add2(p0, p1);
            kk = add2(kk, __shfl_down_sync(0xffffffffu, kk, 4));

            if (lane < LAT) {
                u64 ztn;
                if (e == 0)      { kacc = kk;                        ztn = fma2(hdt, kk, zc); }
                else if (e == 1) { kacc = fma2(dup2(2.f), kk, kacc); ztn = fma2(hdt, kk, zc); }
                else if (e == 2) { kacc = fma2(dup2(2.f), kk, kacc); ztn = fma2(fdt, kk, zc); }
                else             { kacc = add2(kacc, kk);
                                   zc  = fma2(sdt, kacc, zc);
                                   ztn = zc; }
                ((u64*)sw)[lane] = ztn;
            }
            __syncwarp();
        }
        if (lane < LAT) {
            float lo, hi; unpack2(zc, lo, hi);
            g_predz[((size_t)b0 * NT + t + 1) * LAT + lane] = lo;
            g_predz[((size_t)b1 * NT + t + 1) * LAT + lane] = hi;
        }
    }
}

// ---------------------------------------------------------------------------
// Kernel 3: decoder — fully parallel over (b, t).
// ---------------------------------------------------------------------------
__global__ __launch_bounds__(256)
void dec_kernel(const float* __restrict__ d1_w, const float* __restrict__ d1_b,
                const float* __restrict__ d2_w, const float* __restrict__ d2_b,
                float* __restrict__ out)
{
    __shared__ float sw1[LAT * NH], sb1[NH], sw2[NH * OBS], sb2[OBS];
    if (threadIdx.x < LAT * NH) sw1[threadIdx.x] = d1_w[threadIdx.x];
    if (threadIdx.x < NH)       sb1[threadIdx.x] = d1_b[threadIdx.x];
    if (threadIdx.x < NH * OBS) sw2[threadIdx.x] = d2_w[threadIdx.x];
    if (threadIdx.x < OBS)      sb2[threadIdx.x] = d2_b[threadIdx.x];
    __syncthreads();

    int idx = blockIdx.x * blockDim.x + threadIdx.x;   // < NB*NT
    float4 z = *(const float4*)&g_predz[(size_t)idx * LAT];

    float acc0 = sb2[0], acc1 = sb2[1];
#pragma unroll
    for (int jj = 0; jj < NH; ++jj) {
        float h = fmaf(z.x, sw1[0 * NH + jj],
                  fmaf(z.y, sw1[1 * NH + jj],
                  fmaf(z.z, sw1[2 * NH + jj],
                  fmaf(z.w, sw1[3 * NH + jj], sb1[jj]))));
        h = fmaxf(h, 0.f);
        acc0 = fmaf(h, sw2[jj * OBS + 0], acc0);
        acc1 = fmaf(h, sw2[jj * OBS + 1], acc1);
    }
    ((float2*)out)[idx] = make_float2(acc0, acc1);
}

// ---------------------------------------------------------------------------
extern "C" void kernel_launch(void* const* d_in, const int* in_sizes, int n_in,
                              void* d_out, int out_size)
{
    const float* samp_trajs = (const float*)d_in[0];
    const float* samp_ts    = (const float*)d_in[1];
    const float* epsilon    = (const float*)d_in[2];
    const float* i2h_w      = (const float*)d_in[3];
    const float* i2h_b      = (const float*)d_in[4];
    const float* h2o_w      = (const float*)d_in[5];
    const float* h2o_b      = (const float*)d_in[6];
    const float* f1_w       = (const float*)d_in[7];
    const float* f1_b       = (const float*)d_in[8];
    const float* f2_w       = (const float*)d_in[9];
    const float* f2_b       = (const float*)d_in[10];
    const float* f3_w       = (const float*)d_in[11];
    const float* f3_b       = (const float*)d_in[12];
    const float* d1_w       = (const float*)d_in[13];
    const float* d1_b       = (const float*)d_in[14];
    const float* d2_w       = (const float*)d_in[15];
    const float* d2_b       = (const float*)d_in[16];
    float* out = (float*)d_out;

    rnn_kernel<<<NBLK, NWPB * 32>>>(samp_trajs, epsilon, i2h_w, i2h_b, h2o_w, h2o_b, out);
    ode_kernel<<<NBLK, NWPB * 32>>>(samp_ts, f1_w, f1_b, f2_w, f2_b, f3_w, f3_b);
    dec_kernel<<<(NB * NT) / 256, 256>>>(d1_w, d1_b, d2_w, d2_b, out);
}